// round 7
// baseline (speedup 1.0000x reference)
#include <cuda_runtime.h>
#include <cuda_bf16.h>
#include <mma.h>
#include <math.h>
#include <math_constants.h>
#include <stdint.h>

using namespace nvcuda;

// Problem constants
#define HH    16
#define DD    64
#define HIDN  1024
#define NROWS 65536         // B*L*H
#define NBL   4096          // B*L
#define NOUT  128           // 2*D

// __device__ scratch (allocation-free rule)
// W chunks: c in 0..15 -> W1 rows [c*64, c*64+64)          (hidden block)
//           c in 16..19 -> W1 rows [1792+(c-16)*64, +64)   (branch tail)
// layout [n*64 + k] (transposed, bf16 hi/lo)
__device__ __nv_bfloat16 g_Whi[20][8192];
__device__ __nv_bfloat16 g_Wlo[20][8192];
__device__ float g_hidp[4][NBL * NOUT];      // K-split partials of hidden@W1[:1024]
__device__ float g_wstat[12 * NOUT];         // fp32 column sums of W1 stat-block rows

// ---------------------------------------------------------------------------
// helpers
// ---------------------------------------------------------------------------
__device__ __forceinline__ uint32_t cvt_bf16x2(float hi_elem, float lo_elem) {
    // bits [15:0] = bf16(lo_elem), [31:16] = bf16(hi_elem)
    uint32_t r;
    asm("cvt.rn.bf16x2.f32 %0, %1, %2;" : "=r"(r) : "f"(hi_elem), "f"(lo_elem));
    return r;
}

// ---------------------------------------------------------------------------
// prep (92 blocks):
//   blocks 0..79:  weight chunk c = bid>>2, quarter q = bid&3 (2048 elems each)
//   blocks 80..91: wstat j = bid-80
// ---------------------------------------------------------------------------
__global__ void prep_kernel(const float* __restrict__ W1) {
    const int bid = blockIdx.x;
    if (bid < 80) {
        const int c = bid >> 2, q = bid & 3;
        const int rowbase = (c < 16) ? c * 64 : (1792 + (c - 16) * 64);
        const int e0 = q * 2048;
        for (int e = e0 + threadIdx.x; e < e0 + 2048; e += 256) {
            const int k = e >> 7, n = e & 127;
            const float x = W1[(size_t)(rowbase + k) * NOUT + n];
            const __nv_bfloat16 hi = __float2bfloat16(x);
            const __nv_bfloat16 lo = __float2bfloat16(x - __bfloat162float(hi));
            g_Whi[c][n * 64 + k] = hi;
            g_Wlo[c][n * 64 + k] = lo;
        }
    } else {
        const int j = bid - 80;
        const int o = threadIdx.x & 127;
        const int half = threadIdx.x >> 7;   // 0/1: split 64-sum into 2x32
        __shared__ float part[256];
        const float* base = W1 + (size_t)(HIDN + j * 64 + half * 32) * NOUT + o;
        float s = 0.f;
#pragma unroll
        for (int d = 0; d < 32; ++d) s += base[(size_t)d * NOUT];
        part[threadIdx.x] = s;
        __syncthreads();
        if (half == 0) g_wstat[j * NOUT + o] = part[o] + part[128 + o];
    }
}

// ---------------------------------------------------------------------------
// shared staging geometry for both wmma kernels
// smem: AH @0 (128x72 bf16 = 18432 B), AL @18432, BH @36864, BL @55296
//       (hid kernel: total 73728; main adds epilogue arrays on top)
// ---------------------------------------------------------------------------
#define ALD 72     // A/B smem leading dim (bf16 elements)
#define DLD 136    // main: D smem leading dim (floats)

#define OFF_AH   0
#define OFF_AL   18432
#define OFF_BH   36864
#define OFF_BL   55296
#define HID_SMEM_BYTES 73728

// main-only extra regions
#define OFF_WST  73728
#define OFF_SST  79872
#define OFF_W2   86016
#define OFF_HIDC 88064
#define OFF_SLOG 92160
#define MAIN_SMEM_BYTES 96256

// Stage a 128x64 fp32 tile (row stride = srcStride) into AH/AL as bf16 hi/lo.
// Thread mapping: arow = tid>>1 (0..127), half = tid&1, kbase = half*32.
__device__ __forceinline__ void stage_A_hilo(const float* __restrict__ src0,
                                             size_t srcStride,
                                             __nv_bfloat16* AH, __nv_bfloat16* AL,
                                             int tid) {
    const int arow = tid >> 1;
    const int kbase = (tid & 1) * 32;
    const float* src = src0 + (size_t)arow * srcStride + kbase;
#pragma unroll
    for (int j = 0; j < 8; ++j) {
        const float4 v = *reinterpret_cast<const float4*>(src + j * 4);
        const uint32_t h0 = cvt_bf16x2(v.y, v.x);
        const uint32_t h1 = cvt_bf16x2(v.w, v.z);
        const float r0 = v.x - __uint_as_float(h0 << 16);
        const float r1 = v.y - __uint_as_float(h0 & 0xffff0000u);
        const float r2 = v.z - __uint_as_float(h1 << 16);
        const float r3 = v.w - __uint_as_float(h1 & 0xffff0000u);
        const uint32_t l0 = cvt_bf16x2(r1, r0);
        const uint32_t l1 = cvt_bf16x2(r3, r2);
        const int eoff = arow * ALD + kbase + j * 4;
        uint2 hv = {h0, h1}, lv = {l0, l1};
        *reinterpret_cast<uint2*>(&AH[eoff]) = hv;
        *reinterpret_cast<uint2*>(&AL[eoff]) = lv;
    }
}

// Copy one precomputed B chunk (8192 bf16) into padded smem.
__device__ __forceinline__ void stage_B(const __nv_bfloat16* __restrict__ srcH,
                                        const __nv_bfloat16* __restrict__ srcL,
                                        __nv_bfloat16* BH, __nv_bfloat16* BL,
                                        int tid) {
    const int n = tid >> 1;
    const int kb = (tid & 1) * 32;
    const uint4* sH = reinterpret_cast<const uint4*>(srcH + n * 64 + kb);
    const uint4* sL = reinterpret_cast<const uint4*>(srcL + n * 64 + kb);
    uint4* dH = reinterpret_cast<uint4*>(&BH[n * ALD + kb]);
    uint4* dL = reinterpret_cast<uint4*>(&BL[n * ALD + kb]);
#pragma unroll
    for (int q = 0; q < 4; ++q) { dH[q] = sH[q]; dL[q] = sL[q]; }
}

// One 64-K-chunk of hi/lo HMMA into acc[2][4] for warp (wm, wn).
__device__ __forceinline__ void hmma_chunk(
    const __nv_bfloat16* AH, const __nv_bfloat16* AL,
    const __nv_bfloat16* BH, const __nv_bfloat16* BL,
    int wm, int wn,
    wmma::fragment<wmma::accumulator, 16, 16, 16, float> (&acc)[2][4]) {
#pragma unroll
    for (int kk = 0; kk < 4; ++kk) {
        wmma::fragment<wmma::matrix_a, 16, 16, 16, __nv_bfloat16, wmma::row_major> ahi[2], alo[2];
#pragma unroll
        for (int i = 0; i < 2; ++i) {
            const int ro = (wm * 32 + i * 16) * ALD + kk * 16;
            wmma::load_matrix_sync(ahi[i], AH + ro, ALD);
            wmma::load_matrix_sync(alo[i], AL + ro, ALD);
        }
#pragma unroll
        for (int j = 0; j < 4; ++j) {
            wmma::fragment<wmma::matrix_b, 16, 16, 16, __nv_bfloat16, wmma::col_major> bhi, blo;
            const int bo = (wn * 64 + j * 16) * ALD + kk * 16;
            wmma::load_matrix_sync(bhi, BH + bo, ALD);
            wmma::load_matrix_sync(blo, BL + bo, ALD);
#pragma unroll
            for (int i = 0; i < 2; ++i) {
                wmma::mma_sync(acc[i][j], ahi[i], bhi, acc[i][j]);
                wmma::mma_sync(acc[i][j], alo[i], bhi, acc[i][j]);
                wmma::mma_sync(acc[i][j], ahi[i], blo, acc[i][j]);
            }
        }
    }
}

// ---------------------------------------------------------------------------
// hid: g_hidp[ks] = hidden[:, ks*256:(ks+1)*256] @ W1[ks*256:(ks+1)*256, :128]
// wmma bf16 hi/lo. Grid 128 = 32 M-tiles x 4 K-splits. 8 warps, 4(M)x2(N).
// ---------------------------------------------------------------------------
__global__ __launch_bounds__(256, 2)
void hid_wmma_kernel(const float* __restrict__ hidden) {
    extern __shared__ char smc[];
    __nv_bfloat16* AH = reinterpret_cast<__nv_bfloat16*>(smc + OFF_AH);
    __nv_bfloat16* AL = reinterpret_cast<__nv_bfloat16*>(smc + OFF_AL);
    __nv_bfloat16* BH = reinterpret_cast<__nv_bfloat16*>(smc + OFF_BH);
    __nv_bfloat16* BL = reinterpret_cast<__nv_bfloat16*>(smc + OFF_BL);

    const int tid = threadIdx.x;
    const int wid = tid >> 5;
    const int rg  = blockIdx.x >> 2;     // M tile (0..31)
    const int ks  = blockIdx.x & 3;      // K split (0..3)
    const int m0  = rg * 128;
    const int wm  = wid & 3, wn = wid >> 2;

    wmma::fragment<wmma::accumulator, 16, 16, 16, float> acc[2][4];
#pragma unroll
    for (int i = 0; i < 2; ++i)
#pragma unroll
        for (int j = 0; j < 4; ++j) wmma::fill_fragment(acc[i][j], 0.0f);

#pragma unroll 1
    for (int t = 0; t < 4; ++t) {
        const int c = ks * 4 + t;        // weight chunk 0..15
        stage_A_hilo(hidden + (size_t)m0 * HIDN + c * 64, HIDN, AH, AL, tid);
        stage_B(g_Whi[c], g_Wlo[c], BH, BL, tid);
        __syncthreads();
        hmma_chunk(AH, AL, BH, BL, wm, wn, acc);
        __syncthreads();
    }

    float* outp = g_hidp[ks] + (size_t)m0 * NOUT;
#pragma unroll
    for (int i = 0; i < 2; ++i)
#pragma unroll
        for (int j = 0; j < 4; ++j)
            wmma::store_matrix_sync(outp + (wm * 32 + i * 16) * NOUT + wn * 64 + j * 16,
                                    acc[i][j], NOUT, wmma::mem_row_major);
}

// ---------------------------------------------------------------------------
// main: branch GEMM (wmma bf16 hi/lo) + stats + epilogue.
// ---------------------------------------------------------------------------
__global__ __launch_bounds__(256, 2)
void main_wmma_kernel(const float* __restrict__ br0, const float* __restrict__ br1,
                      const float* __restrict__ br2, const float* __restrict__ br3,
                      const float* __restrict__ b1,  const float* __restrict__ W2,
                      const float* __restrict__ b2,  const float* __restrict__ eps_floor,
                      const float* __restrict__ temp, float* __restrict__ out) {
    extern __shared__ char smc[];
    __nv_bfloat16* AH = reinterpret_cast<__nv_bfloat16*>(smc + OFF_AH);
    __nv_bfloat16* AL = reinterpret_cast<__nv_bfloat16*>(smc + OFF_AL);
    __nv_bfloat16* BH = reinterpret_cast<__nv_bfloat16*>(smc + OFF_BH);
    __nv_bfloat16* BL = reinterpret_cast<__nv_bfloat16*>(smc + OFF_BL);
    float* Ds    = reinterpret_cast<float*>(smc);             // epilogue overlay
    float* sWst  = reinterpret_cast<float*>(smc + OFF_WST);
    float* sStat = reinterpret_cast<float*>(smc + OFF_SST);
    float* sW2   = reinterpret_cast<float*>(smc + OFF_W2);
    float* hidc  = reinterpret_cast<float*>(smc + OFF_HIDC);
    float* sLog  = reinterpret_cast<float*>(smc + OFF_SLOG);

    const int tid = threadIdx.x;
    const int wid = tid >> 5;
    const int m0  = blockIdx.x * 128;
    const int wm  = wid & 3, wn = wid >> 2;

    // Prologue one-time loads (covered by chunk-0 __syncthreads)
    for (int i = tid; i < 1024; i += 256) {
        const size_t g = (size_t)(blockIdx.x * 8) * NOUT + i;
        hidc[i] = (g_hidp[0][g] + g_hidp[1][g]) + (g_hidp[2][g] + g_hidp[3][g])
                  + b1[i & 127];
    }
    for (int i = tid; i < 512; i += 256)       sW2[i]  = W2[i];
    for (int i = tid; i < 12 * NOUT; i += 256) sWst[i] = g_wstat[i];

    wmma::fragment<wmma::accumulator, 16, 16, 16, float> acc[2][4];
#pragma unroll
    for (int i = 0; i < 2; ++i)
#pragma unroll
        for (int j = 0; j < 4; ++j) wmma::fill_fragment(acc[i][j], 0.0f);

    const int arow  = tid >> 1;
    const int ahalf = tid & 1;
    const int kbase = ahalf * 32;

#pragma unroll 1
    for (int p = 0; p < 4; ++p) {
        const float* brp = (p == 0) ? br0 : (p == 1) ? br1 : (p == 2) ? br2 : br3;
        // stage A + stats (fused over the same loaded data)
        {
            const float* src = brp + (size_t)(m0 + arow) * DD + kbase;
            float s = 0.f, sq = 0.f, mx = -CUDART_INF_F;
#pragma unroll
            for (int j = 0; j < 8; ++j) {
                const float4 v = *reinterpret_cast<const float4*>(src + j * 4);
                s += (v.x + v.y) + (v.z + v.w);
                sq = fmaf(v.x, v.x, sq); sq = fmaf(v.y, v.y, sq);
                sq = fmaf(v.z, v.z, sq); sq = fmaf(v.w, v.w, sq);
                mx = fmaxf(mx, fmaxf(fmaxf(v.x, v.y), fmaxf(v.z, v.w)));
                const uint32_t h0 = cvt_bf16x2(v.y, v.x);
                const uint32_t h1 = cvt_bf16x2(v.w, v.z);
                const float r0 = v.x - __uint_as_float(h0 << 16);
                const float r1 = v.y - __uint_as_float(h0 & 0xffff0000u);
                const float r2 = v.z - __uint_as_float(h1 << 16);
                const float r3 = v.w - __uint_as_float(h1 & 0xffff0000u);
                const uint32_t l0 = cvt_bf16x2(r1, r0);
                const uint32_t l1 = cvt_bf16x2(r3, r2);
                const int eoff = arow * ALD + kbase + j * 4;
                uint2 hv = {h0, h1}, lv = {l0, l1};
                *reinterpret_cast<uint2*>(&AH[eoff]) = hv;
                *reinterpret_cast<uint2*>(&AL[eoff]) = lv;
            }
            s  += __shfl_xor_sync(0xffffffffu, s, 1);
            sq += __shfl_xor_sync(0xffffffffu, sq, 1);
            mx  = fmaxf(mx, __shfl_xor_sync(0xffffffffu, mx, 1));
            if (ahalf == 0) {
                sStat[arow * 12 + p * 3 + 0] = s * (1.f / 64.f);
                sStat[arow * 12 + p * 3 + 1] = sqrtf(fmaxf(sq * (1.f / 64.f), 1e-8f));
                sStat[arow * 12 + p * 3 + 2] = mx;
            }
        }
        stage_B(g_Whi[16 + p], g_Wlo[16 + p], BH, BL, tid);
        __syncthreads();
        hmma_chunk(AH, AL, BH, BL, wm, wn, acc);
        __syncthreads();   // done reading A/B before restage (or Ds overlay)
    }

    // store D to smem overlay
#pragma unroll
    for (int i = 0; i < 2; ++i)
#pragma unroll
        for (int j = 0; j < 4; ++j)
            wmma::store_matrix_sync(Ds + (wm * 32 + i * 16) * DLD + wn * 64 + j * 16,
                                    acc[i][j], DLD, wmma::mem_row_major);
    __syncthreads();

    // epilogue: hid + stats, gelu, @W2 partials
    {
        const int row  = tid >> 1;
        const int half = tid & 1;
        const int c0   = half * 64;
        const float* hrow = &hidc[(row >> 4) * 128];
        const float* drow = &Ds[row * DLD];
        float st[12];
#pragma unroll
        for (int j = 0; j < 12; ++j) st[j] = sStat[row * 12 + j];
        float lg0 = 0.f, lg1 = 0.f, lg2 = 0.f, lg3 = 0.f;
#pragma unroll 8
        for (int ci = 0; ci < 64; ++ci) {
            const int cc = c0 + ci;
            float a = drow[cc] + hrow[cc];
#pragma unroll
            for (int j = 0; j < 12; ++j) a = fmaf(st[j], sWst[j * NOUT + cc], a);
            a *= normcdff(a);                      // exact gelu
            const float4 w = *reinterpret_cast<const float4*>(&sW2[cc * 4]);
            lg0 = fmaf(a, w.x, lg0);
            lg1 = fmaf(a, w.y, lg1);
            lg2 = fmaf(a, w.z, lg2);
            lg3 = fmaf(a, w.w, lg3);
        }
        sLog[row * 8 + half * 4 + 0] = lg0;
        sLog[row * 8 + half * 4 + 1] = lg1;
        sLog[row * 8 + half * 4 + 2] = lg2;
        sLog[row * 8 + half * 4 + 3] = lg3;
    }
    __syncthreads();

    // softmax / floor / renorm
    if (tid < 128) {
        const int m = m0 + tid;
        const int head = m & (HH - 1);
        float l0 = sLog[tid * 8 + 0] + sLog[tid * 8 + 4] + b2[0];
        float l1 = sLog[tid * 8 + 1] + sLog[tid * 8 + 5] + b2[1];
        float l2 = sLog[tid * 8 + 2] + sLog[tid * 8 + 6] + b2[2];
        float l3 = sLog[tid * 8 + 3] + sLog[tid * 8 + 7] + b2[3];
        const float t = fminf(fmaxf(temp[head], 0.2f), 10.f);
        const float inv_t = 1.f / t;
        const float mxl = fmaxf(fmaxf(l0, l1), fmaxf(l2, l3));
        const float e0 = expf((l0 - mxl) * inv_t);
        const float e1 = expf((l1 - mxl) * inv_t);
        const float e2 = expf((l2 - mxl) * inv_t);
        const float e3 = expf((l3 - mxl) * inv_t);
        const float inv = 1.f / (e0 + e1 + e2 + e3);
        float w0 = e0 * inv, w1 = e1 * inv, w2 = e2 * inv, w3 = e3 * inv;
        const float* ef = &eps_floor[head * 4];
        w0 = fmaxf(w0, fminf(fmaxf(ef[0], 1e-7f), 0.1f));
        w1 = fmaxf(w1, fminf(fmaxf(ef[1], 1e-7f), 0.1f));
        w2 = fmaxf(w2, fminf(fmaxf(ef[2], 1e-7f), 0.1f));
        w3 = fmaxf(w3, fminf(fmaxf(ef[3], 1e-7f), 0.1f));
        const float inv2 = 1.f / (w0 + w1 + w2 + w3);
        float4 o = {w0 * inv2, w1 * inv2, w2 * inv2, w3 * inv2};
        *reinterpret_cast<float4*>(&out[(size_t)m * 4]) = o;
    }
}

// ---------------------------------------------------------------------------
// Launch
// ---------------------------------------------------------------------------
extern "C" void kernel_launch(void* const* d_in, const int* in_sizes, int n_in,
                              void* d_out, int out_size) {
    const float* hidden = (const float*)d_in[0];
    const float* br0    = (const float*)d_in[1];
    const float* br1    = (const float*)d_in[2];
    const float* br2    = (const float*)d_in[3];
    const float* br3    = (const float*)d_in[4];
    const float* W1     = (const float*)d_in[5];
    const float* b1     = (const float*)d_in[6];
    const float* W2     = (const float*)d_in[7];
    const float* b2     = (const float*)d_in[8];
    const float* epsf   = (const float*)d_in[9];
    const float* temp   = (const float*)d_in[10];
    float* out = (float*)d_out;

    cudaFuncSetAttribute(hid_wmma_kernel, cudaFuncAttributeMaxDynamicSharedMemorySize,
                         HID_SMEM_BYTES);
    cudaFuncSetAttribute(main_wmma_kernel, cudaFuncAttributeMaxDynamicSharedMemorySize,
                         MAIN_SMEM_BYTES);

    prep_kernel<<<92, 256>>>(W1);
    hid_wmma_kernel<<<128, 256, HID_SMEM_BYTES>>>(hidden);
    main_wmma_kernel<<<NROWS / 128, 256, MAIN_SMEM_BYTES>>>(br0, br1, br2, br3, b1,
                                                            W2, b2, epsf, temp, out);
}